// round 1
// baseline (speedup 1.0000x reference)
#include <cuda_runtime.h>

#define EPS 1e-5f
#define SLOPE 0.01f
#define BATCH 4096

// ---------------- scratch (device globals; no allocation allowed) ----------
__device__ float g_h1[(size_t)BATCH * 64];
__device__ float g_h2[(size_t)BATCH * 256];
__device__ float g_h3[(size_t)BATCH * 1024];
__device__ float g_x [(size_t)BATCH * 4096];
__device__ float g_t1[(size_t)BATCH * 128 * 64];
__device__ float g_t2[(size_t)BATCH * 256 * 64];

__device__ __forceinline__ float leaky(float v) { return v > 0.f ? v : SLOPE * v; }

// ---------------------------------------------------------------------------
// SGEMM:  C[m][n] = leaky( sum_k A[m][k] * W[n][k] + bias[n] )
// A: M x K row-major, W: N x K row-major. M % 128 == 0, K % 8 == 0, N % 8 == 0.
// Block tile 128x128x8, 256 threads, 8x8 per-thread register tile.
// ---------------------------------------------------------------------------
__global__ __launch_bounds__(256) void sgemm_leaky_k(
    int M, int N, int K,
    const float* __restrict__ A, const float* __restrict__ W,
    const float* __restrict__ bias, float* __restrict__ C)
{
    __shared__ float As[8][128];
    __shared__ float Bs[8][128];

    const int tid  = threadIdx.x;
    const int crow = blockIdx.y * 128;
    const int ccol = blockIdx.x * 128;
    const int aRow = tid >> 1;            // 0..127
    const int aCol = (tid & 1) * 4;       // 0 or 4
    const int tr   = tid >> 4;            // 0..15 (m-group)
    const int tc   = tid & 15;            // 0..15 (n-group)

    float acc[8][8];
#pragma unroll
    for (int i = 0; i < 8; i++)
#pragma unroll
        for (int j = 0; j < 8; j++) acc[i][j] = 0.f;

    for (int k0 = 0; k0 < K; k0 += 8) {
        float4 av = *(const float4*)(A + (size_t)(crow + aRow) * K + k0 + aCol);
        As[aCol + 0][aRow] = av.x;
        As[aCol + 1][aRow] = av.y;
        As[aCol + 2][aRow] = av.z;
        As[aCol + 3][aRow] = av.w;

        float4 bv = make_float4(0.f, 0.f, 0.f, 0.f);
        if (ccol + aRow < N)
            bv = *(const float4*)(W + (size_t)(ccol + aRow) * K + k0 + aCol);
        Bs[aCol + 0][aRow] = bv.x;
        Bs[aCol + 1][aRow] = bv.y;
        Bs[aCol + 2][aRow] = bv.z;
        Bs[aCol + 3][aRow] = bv.w;
        __syncthreads();

#pragma unroll
        for (int k = 0; k < 8; k++) {
            float4 a0 = *(const float4*)&As[k][tr * 8];
            float4 a1 = *(const float4*)&As[k][tr * 8 + 4];
            float4 b0 = *(const float4*)&Bs[k][tc * 8];
            float4 b1 = *(const float4*)&Bs[k][tc * 8 + 4];
            float am[8] = {a0.x, a0.y, a0.z, a0.w, a1.x, a1.y, a1.z, a1.w};
            float bn[8] = {b0.x, b0.y, b0.z, b0.w, b1.x, b1.y, b1.z, b1.w};
#pragma unroll
            for (int i = 0; i < 8; i++)
#pragma unroll
                for (int j = 0; j < 8; j++) acc[i][j] += am[i] * bn[j];
        }
        __syncthreads();
    }

    // epilogue: each thread owns 8 consecutive n at 8 rows -> float4 stores
    const int nbase = ccol + tc * 8;
    if (nbase < N) {                       // N % 8 == 0 -> whole 8-run in range
        float bb[8];
#pragma unroll
        for (int j = 0; j < 8; j++) bb[j] = bias[nbase + j];
#pragma unroll
        for (int i = 0; i < 8; i++) {
            const int m = crow + tr * 8 + i;
            float v[8];
#pragma unroll
            for (int j = 0; j < 8; j++) v[j] = leaky(acc[i][j] + bb[j]);
            float* cp = C + (size_t)m * N + nbase;
            *(float4*)(cp)     = make_float4(v[0], v[1], v[2], v[3]);
            *(float4*)(cp + 4) = make_float4(v[4], v[5], v[6], v[7]);
        }
    }
}

// ---------------------------------------------------------------------------
// BinaryTreeConv for one layer.
//   out[b][o][0]      = 0
//   out[b][o][1 + n]  = sum_{c,k} w[o][c][k] * x[b][c][ idx[b][3n+k] ] + bias[o]
// x: [B][C][64], w: [O][C][3], idx: [B][189] (values 0..63), out: [B][O][64].
// Grid: (O/128, B). Block: 128 threads. Each thread: 8 o x 8 n register tile.
// ---------------------------------------------------------------------------
template <int C, int O>
__global__ __launch_bounds__(128) void conv_kernel(
    const float* __restrict__ x, const int* __restrict__ idx_g,
    const float* __restrict__ w, const float* __restrict__ bias,
    float* __restrict__ out)
{
    constexpr int CC = 16;         // channels per chunk
    constexpr int J  = CC * 3;     // 48 flattened (c,k) per chunk

    __shared__ int   idxs[192];
    __shared__ float xs[CC][64];
    __shared__ float eg[J][64];
    __shared__ float ws[J][128];

    const int b   = blockIdx.y;
    const int o0  = blockIdx.x * 128;
    const int tid = threadIdx.x;
    const int tx  = tid & 7;       // n sub-group
    const int ty  = tid >> 3;      // o group (0..15)

    // load + pad indexes (pad -> 0 for the masked n==63 lane)
    idxs[tid] = idx_g[(size_t)b * 189 + tid];                  // 0..127
    if (tid < 64) idxs[128 + tid] = (128 + tid < 189) ? idx_g[(size_t)b * 189 + 128 + tid] : 0;

    float acc[8][8];
#pragma unroll
    for (int i = 0; i < 8; i++)
#pragma unroll
        for (int t = 0; t < 8; t++) acc[i][t] = 0.f;

    const float* xb = x + (size_t)b * C * 64;

    for (int c0 = 0; c0 < C; c0 += CC) {
        __syncthreads();   // protect smem reuse (also orders idxs on first iter)

        // stage x chunk: CC*64 = 1024 floats = 256 float4
        {
            const float4* xsrc = (const float4*)(xb + (size_t)c0 * 64);
            float4* xd = (float4*)&xs[0][0];
            xd[tid]       = xsrc[tid];
            xd[tid + 128] = xsrc[tid + 128];
        }
        // stage W chunk: 128 rows x 48 floats = 1536 float4-chunks/4 -> 12/thread
        {
            const float* wbase = w + (size_t)o0 * (C * 3) + (size_t)c0 * 3;
#pragma unroll
            for (int t = 0; t < 12; t++) {
                int fi = tid + 128 * t;          // 0..1535 float4 index
                int ol = fi / 12;
                int jj = fi % 12;
                float4 v = *(const float4*)(wbase + (size_t)ol * (C * 3) + jj * 4);
                ws[jj * 4 + 0][ol] = v.x;
                ws[jj * 4 + 1][ol] = v.y;
                ws[jj * 4 + 2][ol] = v.z;
                ws[jj * 4 + 3][ol] = v.w;
            }
        }
        __syncthreads();

        // build gathered E: eg[j][n] = xs[j/3][ idxs[3n + j%3] ], 3072 elems
#pragma unroll
        for (int t = 0; t < 24; t++) {
            int e = tid + 128 * t;
            int j = e >> 6;
            int n = e & 63;
            int c = j / 3;
            int k = j - 3 * c;
            eg[j][n] = xs[c][idxs[3 * n + k]];
        }
        __syncthreads();

        // compute: 64 FMA per 16 smem floats per j-step
#pragma unroll 4
        for (int j = 0; j < J; j++) {
            float4 w0 = *(const float4*)&ws[j][ty * 8];
            float4 w1 = *(const float4*)&ws[j][ty * 8 + 4];
            float wv[8] = {w0.x, w0.y, w0.z, w0.w, w1.x, w1.y, w1.z, w1.w};
            float ev[8];
#pragma unroll
            for (int t = 0; t < 8; t++) ev[t] = eg[j][tx + 8 * t];
#pragma unroll
            for (int i = 0; i < 8; i++)
#pragma unroll
                for (int t = 0; t < 8; t++) acc[i][t] += wv[i] * ev[t];
        }
    }

    // store: slot0 = 0, node n -> slot n+1 ; n == 63 lane is masked
    float* ob = out + (size_t)b * O * 64;
#pragma unroll
    for (int i = 0; i < 8; i++) {
        const int o = o0 + ty * 8 + i;
        const float bb = bias[o];
        if (tx == 0) ob[(size_t)o * 64] = 0.f;
#pragma unroll
        for (int t = 0; t < 8; t++) {
            int n = tx + 8 * t;
            if (n < 63) ob[(size_t)o * 64 + 1 + n] = acc[i][t] + bb;
        }
    }
}

// ---------------------------------------------------------------------------
// TreeLayerNorm + LeakyReLU, in place. One CTA per sample, NT = O*64 elements.
// var uses ddof=1; eps added to STD (matches reference).
// ---------------------------------------------------------------------------
__global__ __launch_bounds__(256) void ln_leaky_k(float* __restrict__ t, int NT)
{
    float* p = t + (size_t)blockIdx.x * NT;
    const int tid = threadIdx.x;

    float s = 0.f, s2 = 0.f;
    for (int i = tid * 4; i < NT; i += 1024) {
        float4 v = *(const float4*)(p + i);
        s  += v.x + v.y + v.z + v.w;
        s2 += v.x * v.x + v.y * v.y + v.z * v.z + v.w * v.w;
    }
    __shared__ float sh[512];
    sh[tid] = s;
    sh[256 + tid] = s2;
    __syncthreads();
    for (int off = 128; off > 0; off >>= 1) {
        if (tid < off) {
            sh[tid]       += sh[tid + off];
            sh[256 + tid] += sh[256 + tid + off];
        }
        __syncthreads();
    }
    const float S = sh[0], S2 = sh[256];
    const float n = (float)NT;
    const float mean = S / n;
    float var = (S2 - S * mean) / (n - 1.f);
    var = fmaxf(var, 0.f);
    const float inv = 1.f / (sqrtf(var) + EPS);

    for (int i = tid * 4; i < NT; i += 1024) {
        float4 v = *(const float4*)(p + i);
        v.x = leaky((v.x - mean) * inv);
        v.y = leaky((v.y - mean) * inv);
        v.z = leaky((v.z - mean) * inv);
        v.w = leaky((v.w - mean) * inv);
        *(float4*)(p + i) = v;
    }
}

// ---------------------------------------------------------------------------
extern "C" void kernel_launch(void* const* d_in, const int* in_sizes, int n_in,
                              void* d_out, int out_size)
{
    const float* trees   = (const float*)d_in[0];
    const int*   indexes = (const int*)  d_in[1];
    const float* W1 = (const float*)d_in[2];  const float* b1 = (const float*)d_in[3];
    const float* W2 = (const float*)d_in[4];  const float* b2 = (const float*)d_in[5];
    const float* W3 = (const float*)d_in[6];  const float* b3 = (const float*)d_in[7];
    const float* W4 = (const float*)d_in[8];  const float* b4 = (const float*)d_in[9];
    const float* cw1 = (const float*)d_in[10]; const float* cb1 = (const float*)d_in[11];
    const float* cw2 = (const float*)d_in[12]; const float* cb2 = (const float*)d_in[13];
    const float* cw3 = (const float*)d_in[14]; const float* cb3 = (const float*)d_in[15];
    float* out = (float*)d_out;

    float *h1, *h2, *h3, *xx, *t1, *t2;
    cudaGetSymbolAddress((void**)&h1, g_h1);
    cudaGetSymbolAddress((void**)&h2, g_h2);
    cudaGetSymbolAddress((void**)&h3, g_h3);
    cudaGetSymbolAddress((void**)&xx, g_x);
    cudaGetSymbolAddress((void**)&t1, g_t1);
    cudaGetSymbolAddress((void**)&t2, g_t2);

    // MLP stack (leaky fused)
    sgemm_leaky_k<<<dim3(1, 32),  256>>>(BATCH,   64,   16, trees, W1, b1, h1);
    sgemm_leaky_k<<<dim3(2, 32),  256>>>(BATCH,  256,   64, h1,    W2, b2, h2);
    sgemm_leaky_k<<<dim3(8, 32),  256>>>(BATCH, 1024,  256, h2,    W3, b3, h3);
    sgemm_leaky_k<<<dim3(32, 32), 256>>>(BATCH, 4096, 1024, h3,    W4, b4, xx);

    // Tree conv blocks: conv -> (pad zero slot) -> LayerNorm -> Leaky
    conv_kernel<64, 128> <<<dim3(1, BATCH), 128>>>(xx, indexes, cw1, cb1, t1);
    ln_leaky_k<<<BATCH, 256>>>(t1, 128 * 64);

    conv_kernel<128, 256><<<dim3(2, BATCH), 128>>>(t1, indexes, cw2, cb2, t2);
    ln_leaky_k<<<BATCH, 256>>>(t2, 256 * 64);

    conv_kernel<256, 512><<<dim3(4, BATCH), 128>>>(t2, indexes, cw3, cb3, out);
    ln_leaky_k<<<BATCH, 256>>>(out, 512 * 64);
}

// round 3
// speedup vs baseline: 1.1350x; 1.1350x over previous
#include <cuda_runtime.h>

#define EPS 1e-5f
#define SLOPE 0.01f
#define BATCH 4096

// ---------------- scratch (device globals; no allocation allowed) ----------
__device__ float g_h1[(size_t)BATCH * 64];
__device__ float g_h2[(size_t)BATCH * 256];
__device__ float g_h3[(size_t)BATCH * 1024];
__device__ float g_x [(size_t)BATCH * 4096];
__device__ float g_t1[(size_t)BATCH * 128 * 64];
__device__ float g_t2[(size_t)BATCH * 256 * 64];

__device__ __forceinline__ float leaky(float v) { return v > 0.f ? v : SLOPE * v; }

// packed fp32x2 FMA: d = a*b + d (elementwise on both 32-bit halves).
// Only reachable via PTX; doubles FP32 throughput vs scalar FFMA on sm_103a.
__device__ __forceinline__ void ffma2(unsigned long long& d,
                                      unsigned long long a,
                                      unsigned long long b) {
    asm("fma.rn.f32x2 %0, %1, %2, %0;" : "+l"(d) : "l"(a), "l"(b));
}

// ---------------------------------------------------------------------------
// SGEMM:  C[m][n] = leaky( sum_k A[m][k] * W[n][k] + bias[n] )
// Block tile 128x128x8, 256 threads, 8x8 per-thread tile, FFMA2 inner loop.
// As is staged with duplicated pairs {a,a} so the broadcast operand is a
// plain 8B smem load; Bs pairs along n come free from adjacency.
// ---------------------------------------------------------------------------
__global__ __launch_bounds__(256) void sgemm_leaky_k(
    int M, int N, int K,
    const float* __restrict__ A, const float* __restrict__ W,
    const float* __restrict__ bias, float* __restrict__ C)
{
    __shared__ float As[8][256];   // duplicated: As[k][2m]=As[k][2m+1]=a[m][k]
    __shared__ float Bs[8][128];

    const int tid  = threadIdx.x;
    const int crow = blockIdx.y * 128;
    const int ccol = blockIdx.x * 128;
    const int aRow = tid >> 1;            // 0..127
    const int aCol = (tid & 1) * 4;       // 0 or 4
    const int tr   = tid >> 4;            // 0..15 (m-group)
    const int tc   = tid & 15;            // 0..15 (n-group)

    unsigned long long acc[8][4];
#pragma unroll
    for (int i = 0; i < 8; i++)
#pragma unroll
        for (int j = 0; j < 4; j++) acc[i][j] = 0ull;

    for (int k0 = 0; k0 < K; k0 += 8) {
        float4 av = *(const float4*)(A + (size_t)(crow + aRow) * K + k0 + aCol);
        *(float2*)&As[aCol + 0][2 * aRow] = make_float2(av.x, av.x);
        *(float2*)&As[aCol + 1][2 * aRow] = make_float2(av.y, av.y);
        *(float2*)&As[aCol + 2][2 * aRow] = make_float2(av.z, av.z);
        *(float2*)&As[aCol + 3][2 * aRow] = make_float2(av.w, av.w);

        float4 bv = make_float4(0.f, 0.f, 0.f, 0.f);
        if (ccol + aRow < N)
            bv = *(const float4*)(W + (size_t)(ccol + aRow) * K + k0 + aCol);
        Bs[aCol + 0][aRow] = bv.x;
        Bs[aCol + 1][aRow] = bv.y;
        Bs[aCol + 2][aRow] = bv.z;
        Bs[aCol + 3][aRow] = bv.w;
        __syncthreads();

#pragma unroll
        for (int k = 0; k < 8; k++) {
            const float* ap = &As[k][tr * 16];
            ulonglong2 a01 = *(const ulonglong2*)(ap);
            ulonglong2 a23 = *(const ulonglong2*)(ap + 4);
            ulonglong2 a45 = *(const ulonglong2*)(ap + 8);
            ulonglong2 a67 = *(const ulonglong2*)(ap + 12);
            unsigned long long am[8] = {a01.x, a01.y, a23.x, a23.y,
                                        a45.x, a45.y, a67.x, a67.y};
            ulonglong2 b03 = *(const ulonglong2*)&Bs[k][tc * 8];
            ulonglong2 b47 = *(const ulonglong2*)&Bs[k][tc * 8 + 4];
            unsigned long long bn[4] = {b03.x, b03.y, b47.x, b47.y};
#pragma unroll
            for (int i = 0; i < 8; i++)
#pragma unroll
                for (int j = 0; j < 4; j++) ffma2(acc[i][j], am[i], bn[j]);
        }
        __syncthreads();
    }

    const int nbase = ccol + tc * 8;
    if (nbase < N) {
        float bb[8];
#pragma unroll
        for (int j = 0; j < 8; j++) bb[j] = bias[nbase + j];
#pragma unroll
        for (int i = 0; i < 8; i++) {
            const int m = crow + tr * 8 + i;
            float v[8];
#pragma unroll
            for (int j = 0; j < 4; j++) {
                float2 p = *reinterpret_cast<float2*>(&acc[i][j]);
                v[2 * j]     = leaky(p.x + bb[2 * j]);
                v[2 * j + 1] = leaky(p.y + bb[2 * j + 1]);
            }
            float* cp = C + (size_t)m * N + nbase;
            *(float4*)(cp)     = make_float4(v[0], v[1], v[2], v[3]);
            *(float4*)(cp + 4) = make_float4(v[4], v[5], v[6], v[7]);
        }
    }
}

// ---------------------------------------------------------------------------
// BinaryTreeConv:
//   out[b][o][0]     = 0
//   out[b][o][1 + n] = sum_{c,k} w[o][c][k] * x[b][c][ idx[b][3n+k] ] + bias[o]
// Grid (O/128, B), 128 threads, 8o x 8n per-thread tile, FFMA2 inner loop.
// egd holds the gathered E matrix with each value DUPLICATED ({e,e} pairs) so
// the broadcast operand of FFMA2 is a direct 8B smem load; the o-pair operand
// comes free from adjacent ws[j][o] values.
// ---------------------------------------------------------------------------
template <int C, int O>
__global__ __launch_bounds__(128) void conv_kernel(
    const float* __restrict__ x, const int* __restrict__ idx_g,
    const float* __restrict__ w, const float* __restrict__ bias,
    float* __restrict__ out)
{
    constexpr int CC = 8;          // channels per chunk
    constexpr int J  = CC * 3;     // 24 flattened (c,k) per chunk

    __shared__ int   idxs[192];
    __shared__ float xs[CC][64];        // 2 KB
    __shared__ float egd[J][128];       // duplicated pairs, 12 KB
    __shared__ float ws[J][128];        // 12 KB

    const int b   = blockIdx.y;
    const int o0  = blockIdx.x * 128;
    const int tid = threadIdx.x;
    const int tx  = tid & 7;       // n sub-group
    const int ty  = tid >> 3;      // o group (0..15)

    idxs[tid] = idx_g[(size_t)b * 189 + tid];
    if (tid < 64) idxs[128 + tid] = (128 + tid < 189) ? idx_g[(size_t)b * 189 + 128 + tid] : 0;

    unsigned long long acc[4][8];
#pragma unroll
    for (int i = 0; i < 4; i++)
#pragma unroll
        for (int t = 0; t < 8; t++) acc[i][t] = 0ull;

    const float* xb = x + (size_t)b * C * 64;

    for (int c0 = 0; c0 < C; c0 += CC) {
        __syncthreads();   // protect smem reuse (also orders idxs on first iter)

        // stage x chunk: CC*64 = 512 floats = 128 float4 -> 1 per thread
        ((float4*)&xs[0][0])[tid] = ((const float4*)(xb + (size_t)c0 * 64))[tid];

        // stage W chunk: 128 o-rows x 24 floats = 768 float4 -> 6 per thread
        {
            const float* wbase = w + (size_t)o0 * (C * 3) + (size_t)c0 * 3;
#pragma unroll
            for (int t = 0; t < 6; t++) {
                int fi = tid + 128 * t;          // 0..767
                int ol = fi / 6;
                int jj = fi % 6;
                float4 v = *(const float4*)(wbase + (size_t)ol * (C * 3) + jj * 4);
                ws[jj * 4 + 0][ol] = v.x;
                ws[jj * 4 + 1][ol] = v.y;
                ws[jj * 4 + 2][ol] = v.z;
                ws[jj * 4 + 3][ol] = v.w;
            }
        }
        __syncthreads();

        // build duplicated gathered E: 1536 logical elems -> 12 per thread
#pragma unroll
        for (int t = 0; t < 12; t++) {
            int e = tid + 128 * t;
            int j = e >> 6;
            int n = e & 63;
            int c = j / 3;
            int k = j - 3 * c;
            float v = xs[c][idxs[3 * n + k]];
            *(float2*)&egd[j][2 * n] = make_float2(v, v);
        }
        __syncthreads();

#pragma unroll 3
        for (int j = 0; j < J; j++) {
            ulonglong2 wA = *(const ulonglong2*)&ws[j][ty * 8];
            ulonglong2 wB = *(const ulonglong2*)&ws[j][ty * 8 + 4];
            unsigned long long wp[4] = {wA.x, wA.y, wB.x, wB.y};
            unsigned long long ep[8];
#pragma unroll
            for (int t = 0; t < 8; t++)
                ep[t] = *(const unsigned long long*)&egd[j][2 * (tx + 8 * t)];
#pragma unroll
            for (int i2 = 0; i2 < 4; i2++)
#pragma unroll
                for (int t = 0; t < 8; t++) ffma2(acc[i2][t], wp[i2], ep[t]);
        }
    }

    // store: slot0 = 0, node n -> slot n+1 ; n == 63 lane is masked
    float* ob = out + (size_t)b * O * 64;
#pragma unroll
    for (int i2 = 0; i2 < 4; i2++) {
        const int oA = o0 + ty * 8 + 2 * i2;
        const float bA = bias[oA];
        const float bB = bias[oA + 1];
        if (tx == 0) {
            ob[(size_t)oA * 64]       = 0.f;
            ob[(size_t)(oA + 1) * 64] = 0.f;
        }
#pragma unroll
        for (int t = 0; t < 8; t++) {
            int n = tx + 8 * t;
            float2 p = *reinterpret_cast<float2*>(&acc[i2][t]);
            if (n < 63) {
                ob[(size_t)oA * 64 + 1 + n]       = p.x + bA;
                ob[(size_t)(oA + 1) * 64 + 1 + n] = p.y + bB;
            }
        }
    }
}

// ---------------------------------------------------------------------------
// TreeLayerNorm + LeakyReLU, in place. One CTA per sample.
// var uses ddof=1; eps added to STD (matches reference).
// ---------------------------------------------------------------------------
__global__ __launch_bounds__(256) void ln_leaky_k(float* __restrict__ t, int NT)
{
    float* p = t + (size_t)blockIdx.x * NT;
    const int tid = threadIdx.x;

    float s = 0.f, s2 = 0.f;
    for (int i = tid * 4; i < NT; i += 1024) {
        float4 v = *(const float4*)(p + i);
        s  += v.x + v.y + v.z + v.w;
        s2 += v.x * v.x + v.y * v.y + v.z * v.z + v.w * v.w;
    }
    __shared__ float sh[512];
    sh[tid] = s;
    sh[256 + tid] = s2;
    __syncthreads();
    for (int off = 128; off > 0; off >>= 1) {
        if (tid < off) {
            sh[tid]       += sh[tid + off];
            sh[256 + tid] += sh[256 + tid + off];
        }
        __syncthreads();
    }
    const float S = sh[0], S2 = sh[256];
    const float n = (float)NT;
    const float mean = S / n;
    float var = (S2 - S * mean) / (n - 1.f);
    var = fmaxf(var, 0.f);
    const float inv = 1.f / (sqrtf(var) + EPS);

    for (int i = tid * 4; i < NT; i += 1024) {
        float4 v = *(const float4*)(p + i);
        v.x = leaky((v.x - mean) * inv);
        v.y = leaky((v.y - mean) * inv);
        v.z = leaky((v.z - mean) * inv);
        v.w = leaky((v.w - mean) * inv);
        *(float4*)(p + i) = v;
    }
}

// ---------------------------------------------------------------------------
extern "C" void kernel_launch(void* const* d_in, const int* in_sizes, int n_in,
                              void* d_out, int out_size)
{
    const float* trees   = (const float*)d_in[0];
    const int*   indexes = (const int*)  d_in[1];
    const float* W1 = (const float*)d_in[2];  const float* b1 = (const float*)d_in[3];
    const float* W2 = (const float*)d_in[4];  const float* b2 = (const float*)d_in[5];
    const float* W3 = (const float*)d_in[6];  const float* b3 = (const float*)d_in[7];
    const float* W4 = (const float*)d_in[8];  const float* b4 = (const float*)d_in[9];
    const float* cw1 = (const float*)d_in[10]; const float* cb1 = (const float*)d_in[11];
    const float* cw2 = (const float*)d_in[12]; const float* cb2 = (const float*)d_in[13];
    const float* cw3 = (const float*)d_in[14]; const float* cb3 = (const float*)d_in[15];
    float* out = (float*)d_out;

    float *h1, *h2, *h3, *xx, *t1, *t2;
    cudaGetSymbolAddress((void**)&h1, g_h1);
    cudaGetSymbolAddress((void**)&h2, g_h2);
    cudaGetSymbolAddress((void**)&h3, g_h3);
    cudaGetSymbolAddress((void**)&xx, g_x);
    cudaGetSymbolAddress((void**)&t1, g_t1);
    cudaGetSymbolAddress((void**)&t2, g_t2);

    // MLP stack (leaky fused)
    sgemm_leaky_k<<<dim3(1, 32),  256>>>(BATCH,   64,   16, trees, W1, b1, h1);
    sgemm_leaky_k<<<dim3(2, 32),  256>>>(BATCH,  256,   64, h1,    W2, b2, h2);
    sgemm_leaky_k<<<dim3(8, 32),  256>>>(BATCH, 1024,  256, h2,    W3, b3, h3);
    sgemm_leaky_k<<<dim3(32, 32), 256>>>(BATCH, 4096, 1024, h3,    W4, b4, xx);

    // Tree conv blocks: conv -> (pad zero slot) -> LayerNorm -> Leaky
    conv_kernel<64, 128> <<<dim3(1, BATCH), 128>>>(xx, indexes, cw1, cb1, t1);
    ln_leaky_k<<<BATCH, 256>>>(t1, 128 * 64);

    conv_kernel<128, 256><<<dim3(2, BATCH), 128>>>(t1, indexes, cw2, cb2, t2);
    ln_leaky_k<<<BATCH, 256>>>(t2, 256 * 64);

    conv_kernel<256, 512><<<dim3(4, BATCH), 128>>>(t2, indexes, cw3, cb3, out);
    ln_leaky_k<<<BATCH, 256>>>(out, 512 * 64);
}

// round 6
// speedup vs baseline: 2.8521x; 2.5128x over previous
#include <cuda_runtime.h>
#include <cstdint>

#define EPS 1e-5f
#define SLOPE 0.01f
#define BATCH 4096

// ---------------- scratch (device globals; no allocation allowed) ----------
__device__ float g_h1[(size_t)BATCH * 64];
__device__ float g_h2[(size_t)BATCH * 256];
__device__ float g_h3[(size_t)BATCH * 1024];
__device__ float g_x [(size_t)BATCH * 4096];
__device__ float g_t1[(size_t)BATCH * 128 * 64];
__device__ float g_t2[(size_t)BATCH * 256 * 64];

__device__ __forceinline__ float leaky(float v) { return v > 0.f ? v : SLOPE * v; }

// ---------------- split-bf16 helpers --------------------------------------
// Pack two f32 into bf16x2 (v0 -> low half) and the bf16x2 of the residuals.
// hi+lo carries ~16 mantissa bits -> 3-term MMA gives ~1e-5 relative error.
__device__ __forceinline__ void split2(float v0, float v1, uint32_t& hi, uint32_t& lo) {
    asm("cvt.rn.bf16x2.f32 %0, %1, %2;" : "=r"(hi) : "f"(v1), "f"(v0));
    float h0 = __uint_as_float(hi << 16);
    float h1 = __uint_as_float(hi & 0xFFFF0000u);
    float r0 = v0 - h0, r1 = v1 - h1;
    asm("cvt.rn.bf16x2.f32 %0, %1, %2;" : "=r"(lo) : "f"(r1), "f"(r0));
}

// D(16x8,f32) += A(16x16,bf16) @ B(16x8,bf16)  -- warp-collective
__device__ __forceinline__ void mma4(float* c, uint4 a, uint2 b) {
    asm volatile(
        "mma.sync.aligned.m16n8k16.row.col.f32.bf16.bf16.f32 "
        "{%0,%1,%2,%3}, {%4,%5,%6,%7}, {%8,%9}, {%0,%1,%2,%3};"
        : "+f"(c[0]), "+f"(c[1]), "+f"(c[2]), "+f"(c[3])
        : "r"(a.x), "r"(a.y), "r"(a.z), "r"(a.w), "r"(b.x), "r"(b.y));
}

// ---------------------------------------------------------------------------
// BinaryTreeConv on tensor cores (split-bf16 mma.sync).
//   out[b][o][0]     = 0
//   out[b][o][1 + n] = sum_{c,k} w[o][c][k] * x[b][c][ idx[b][3n+k] ] + bias[o]
// CTA = (o-tile of 128, 2 samples). 8 warps in 2m x 4n grid; each warp owns
// 4 m16-tiles x 4 n8-tiles. K (=3C) chunked by 48 (16 channels). Operands are
// staged in smem pre-permuted into exact m16n8k16 fragment layout.
// ---------------------------------------------------------------------------
template <int C, int O>
__global__ __launch_bounds__(256, 2) void conv_mma(
    const float* __restrict__ x, const int* __restrict__ idx_g,
    const float* __restrict__ w, const float* __restrict__ bias,
    float* __restrict__ out)
{
    constexpr int K3  = 3 * C;
    constexpr int NCH = C / 16;    // K-chunks of 48

    extern __shared__ uint32_t sm[];
    uint32_t* aph = sm;                    // [3kt][8mt][32][4]  = 3072
    uint32_t* apl = aph + 3072;            // 3072
    uint32_t* bph = apl + 3072;            // [2s][3kt][8nt][32][2] = 3072
    uint32_t* bpl = bph + 3072;            // 3072
    float*    xs  = (float*)(bpl + 3072);  // [2][16][64] = 2048 f32
    int*      idxs = (int*)(xs + 2048);    // [2][192]

    const int tid  = threadIdx.x;
    const int wid  = tid >> 5, lane = tid & 31;
    const int g    = lane >> 2, t = lane & 3;
    const int wm   = wid >> 2, wn = wid & 3;
    const int o0   = blockIdx.x * 128;
    const int b0   = blockIdx.y * 2;

    for (int e = tid; e < 384; e += 256) {
        int s = e / 192, p = e - s * 192;
        idxs[e] = (p < 189) ? idx_g[(size_t)(b0 + s) * 189 + p] : 0;
    }

    float acc[4][4][4];
#pragma unroll
    for (int i = 0; i < 4; i++)
#pragma unroll
        for (int j = 0; j < 4; j++)
#pragma unroll
            for (int r = 0; r < 4; r++) acc[i][j][r] = 0.f;

    for (int ch = 0; ch < NCH; ch++) {
        __syncthreads();   // previous chunk's smem fully consumed (also idxs on ch=0)

        // stage x chunk: 2 samples x 16 ch x 64 slots = 512 float4
#pragma unroll
        for (int q = tid; q < 512; q += 256) {
            int s = q >> 8, r = q & 255;
            ((float4*)xs)[q] =
                ((const float4*)(x + ((size_t)(b0 + s) * C + ch * 16) * 64))[r];
        }
        // stage W -> A fragments (768 groups, 3 per thread)
        {
            const float* wb = w + (size_t)o0 * K3 + ch * 48;
#pragma unroll
            for (int q = tid; q < 768; q += 256) {
                int kt = q >> 8, rem = q & 255, mt = rem >> 5, l = rem & 31;
                int gg = l >> 2, tt = l & 3;
                const float* p0 = wb + (size_t)(mt * 16 + gg) * K3 + kt * 16 + tt * 2;
                float2 v00 = *(const float2*)(p0);
                float2 v10 = *(const float2*)(p0 + 8 * K3);
                float2 v01 = *(const float2*)(p0 + 8);
                float2 v11 = *(const float2*)(p0 + 8 * K3 + 8);
                uint32_t h0,l0,h1,l1,h2,l2,h3,l3;
                split2(v00.x, v00.y, h0, l0);
                split2(v10.x, v10.y, h1, l1);
                split2(v01.x, v01.y, h2, l2);
                split2(v11.x, v11.y, h3, l3);
                int base = ((kt * 8 + mt) * 32 + l) * 4;
                *(uint4*)(aph + base) = make_uint4(h0, h1, h2, h3);
                *(uint4*)(apl + base) = make_uint4(l0, l1, l2, l3);
            }
        }
        __syncthreads();   // xs ready for gather

        // gather E -> B fragments (1536 groups, 6 per thread)
#pragma unroll
        for (int q = tid; q < 1536; q += 256) {
            int s = q / 768, rem = q - s * 768;
            int kt = rem >> 8; rem &= 255;
            int nt = rem >> 5, l = rem & 31;
            int gg = l >> 2, tt = l & 3;
            const int*   ip = idxs + s * 192 + 3 * (nt * 8 + gg);
            const float* xp = xs + s * 1024;
            float v[4];
#pragma unroll
            for (int u = 0; u < 4; u++) {
                int kl = kt * 16 + tt * 2 + (u & 1) + (u >> 1) * 8;
                int cl = kl / 3;           // chunk-local channel (48 cols = 16 ch)
                int kk = kl - cl * 3;
                v[u] = xp[cl * 64 + ip[kk]];
            }
            uint32_t bh0, bl0, bh1, bl1;
            split2(v[0], v[1], bh0, bl0);
            split2(v[2], v[3], bh1, bl1);
            int base = ((s * 3 + kt) * 8 + nt) * 64 + l * 2;
            *(uint2*)(bph + base) = make_uint2(bh0, bh1);
            *(uint2*)(bpl + base) = make_uint2(bl0, bl1);
        }
        __syncthreads();   // fragments ready

        // compute: 3 k16-steps x 16 tiles x 3 MMAs
#pragma unroll
        for (int kt = 0; kt < 3; kt++) {
            uint2 bh[4], bl[4];
#pragma unroll
            for (int j = 0; j < 4; j++) {
                int ntg = wn * 4 + j;
                int s = ntg >> 3, nt = ntg & 7;
                int base = ((s * 3 + kt) * 8 + nt) * 64 + lane * 2;
                bh[j] = *(const uint2*)(bph + base);
                bl[j] = *(const uint2*)(bpl + base);
            }
#pragma unroll
            for (int i = 0; i < 4; i++) {
                int mt = wm * 4 + i;
                int base = ((kt * 8 + mt) * 32 + lane) * 4;
                uint4 ah = *(const uint4*)(aph + base);
                uint4 al = *(const uint4*)(apl + base);
#pragma unroll
                for (int j = 0; j < 4; j++) {
                    mma4(acc[i][j], ah, bh[j]);
                    mma4(acc[i][j], ah, bl[j]);
                    mma4(acc[i][j], al, bh[j]);
                }
            }
        }
    }

    // zero slot 0 for all (sample, o) pairs: 256 threads = 2 x 128
    {
        int s = tid >> 7, ol = tid & 127;
        out[((size_t)(b0 + s) * O + o0 + ol) * 64] = 0.f;
    }
    // store: node n -> slot n+1, node 63 discarded
#pragma unroll
    for (int i = 0; i < 4; i++) {
        int mt = wm * 4 + i;
        int or0 = o0 + mt * 16 + g;
        float bs0 = bias[or0], bs1 = bias[or0 + 8];
#pragma unroll
        for (int j = 0; j < 4; j++) {
            int ntg = wn * 4 + j;
            int s = ntg >> 3, nt = ntg & 7;
            int col = nt * 8 + t * 2;
            float* op0 = out + ((size_t)(b0 + s) * O + or0) * 64;
            float* op1 = op0 + 8 * 64;
            op0[1 + col] = acc[i][j][0] + bs0;
            op1[1 + col] = acc[i][j][2] + bs1;
            if (col + 1 < 63) {
                op0[2 + col] = acc[i][j][1] + bs0;
                op1[2 + col] = acc[i][j][3] + bs1;
            }
        }
    }
}

// ---------------------------------------------------------------------------
// GEMM on tensor cores (split-bf16): C[m][n] = leaky(sum_k A[m][k]*W[n][k] + bias[n])
// CTA tile 128m x 128n, K chunked by 64. Same warp layout as conv_mma.
// Requires M % 128 == 0, N % 128 == 0, K % 64 == 0.
// ---------------------------------------------------------------------------
__global__ __launch_bounds__(256, 2) void gemm_mma(
    int M, int N, int K,
    const float* __restrict__ A, const float* __restrict__ W,
    const float* __restrict__ bias, float* __restrict__ Cout)
{
    extern __shared__ uint32_t sm[];
    uint32_t* aph = sm;               // [4kt][8mt][32][4] = 4096
    uint32_t* apl = aph + 4096;
    uint32_t* bph = apl + 4096;       // [4kt][16nt][32][2] = 4096
    uint32_t* bpl = bph + 4096;

    const int tid  = threadIdx.x;
    const int wid  = tid >> 5, lane = tid & 31;
    const int g    = lane >> 2, t = lane & 3;
    const int wm   = wid >> 2, wn = wid & 3;
    const int m0   = blockIdx.y * 128;
    const int n0   = blockIdx.x * 128;

    float acc[4][4][4];
#pragma unroll
    for (int i = 0; i < 4; i++)
#pragma unroll
        for (int j = 0; j < 4; j++)
#pragma unroll
            for (int r = 0; r < 4; r++) acc[i][j][r] = 0.f;

    for (int k0 = 0; k0 < K; k0 += 64) {
        __syncthreads();
        // A fragments: 1024 groups, 4 per thread
#pragma unroll
        for (int q = tid; q < 1024; q += 256) {
            int kt = q >> 8, rem = q & 255, mt = rem >> 5, l = rem & 31;
            int gg = l >> 2, tt = l & 3;
            const float* p0 = A + (size_t)(m0 + mt * 16 + gg) * K + k0 + kt * 16 + tt * 2;
            float2 v00 = *(const float2*)(p0);
            float2 v10 = *(const float2*)(p0 + 8 * (size_t)K);
            float2 v01 = *(const float2*)(p0 + 8);
            float2 v11 = *(const float2*)(p0 + 8 * (size_t)K + 8);
            uint32_t h0,l0,h1,l1,h2,l2,h3,l3;
            split2(v00.x, v00.y, h0, l0);
            split2(v10.x, v10.y, h1, l1);
            split2(v01.x, v01.y, h2, l2);
            split2(v11.x, v11.y, h3, l3);
            int base = ((kt * 8 + mt) * 32 + l) * 4;
            *(uint4*)(aph + base) = make_uint4(h0, h1, h2, h3);
            *(uint4*)(apl + base) = make_uint4(l0, l1, l2, l3);
        }
        // B fragments (W rows are n): 2048 groups, 8 per thread
#pragma unroll
        for (int q = tid; q < 2048; q += 256) {
            int kt = q >> 9, rem = q & 511, nt = rem >> 5, l = rem & 31;
            int gg = l >> 2, tt = l & 3;
            const float* p0 = W + (size_t)(n0 + nt * 8 + gg) * K + k0 + kt * 16 + tt * 2;
            float2 v0 = *(const float2*)(p0);
            float2 v1 = *(const float2*)(p0 + 8);
            uint32_t bh0, bl0, bh1, bl1;
            split2(v0.x, v0.y, bh0, bl0);
            split2(v1.x, v1.y, bh1, bl1);
            int base = (kt * 16 + nt) * 64 + l * 2;
            *(uint2*)(bph + base) = make_uint2(bh0, bh1);
            *(uint2*)(bpl + base) = make_uint2(bl0, bl1);
        }
        __syncthreads();

#pragma unroll
        for (int kt = 0; kt < 4; kt++) {
            uint2 bh[4], bl[4];
#pragma unroll
            for (int j = 0; j < 4; j++) {
                int nt = wn * 4 + j;
                int base = (kt * 16 + nt) * 64 + lane * 2;
                bh[j] = *(const uint2*)(bph + base);
                bl[j] = *(const uint2*)(bpl + base);
            }
#pragma unroll
            for (int i = 0; i < 4; i++) {
                int mt = wm * 4 + i;
                int base = ((kt * 8 + mt) * 32 + lane) * 4;
                uint4 ah = *(const uint4*)(aph + base);
                uint4 al = *(const uint4*)(apl + base);
#pragma unroll
                for (int j = 0; j < 4; j++) {
                    mma4(acc[i][j], ah, bh[j]);
                    mma4(acc[i][j], ah, bl[j]);
                    mma4(acc[i][j], al, bh[j]);
                }
            }
        }
    }

    // epilogue: bias + leaky, float2 stores
#pragma unroll
    for (int i = 0; i < 4; i++) {
        int mr = m0 + (wm * 4 + i) * 16 + g;
        float* r0 = Cout + (size_t)mr * N;
        float* r1 = r0 + 8 * (size_t)N;
#pragma unroll
        for (int j = 0; j < 4; j++) {
            int n = n0 + (wn * 4 + j) * 8 + t * 2;
            float2 bb = *(const float2*)(bias + n);
            float2 u0 = make_float2(leaky(acc[i][j][0] + bb.x), leaky(acc[i][j][1] + bb.y));
            float2 u1 = make_float2(leaky(acc[i][j][2] + bb.x), leaky(acc[i][j][3] + bb.y));
            *(float2*)(r0 + n) = u0;
            *(float2*)(r1 + n) = u1;
        }
    }
}

// ---------------------------------------------------------------------------
// Scalar SGEMM for layer 1 (N=64, K=16 — too small for the mma tile).
// ---------------------------------------------------------------------------
__global__ __launch_bounds__(256) void sgemm_leaky_k(
    int M, int N, int K,
    const float* __restrict__ A, const float* __restrict__ W,
    const float* __restrict__ bias, float* __restrict__ C)
{
    __shared__ float As[8][128];
    __shared__ float Bs[8][128];

    const int tid  = threadIdx.x;
    const int crow = blockIdx.y * 128;
    const int ccol = blockIdx.x * 128;
    const int aRow = tid >> 1;
    const int aCol = (tid & 1) * 4;
    const int tr   = tid >> 4;
    const int tc   = tid & 15;

    float acc[8][8];
#pragma unroll
    for (int i = 0; i < 8; i++)
#pragma unroll
        for (int j = 0; j < 8; j++) acc[i][j] = 0.f;

    for (int k0 = 0; k0 < K; k0 += 8) {
        float4 av = *(const float4*)(A + (size_t)(crow + aRow) * K + k0 + aCol);
        As[aCol + 0][aRow] = av.x;
        As[aCol + 1][aRow] = av.y;
        As[aCol + 2][aRow] = av.z;
        As[aCol + 3][aRow] = av.w;

        float4 bv = make_float4(0.f, 0.f, 0.f, 0.f);
        if (ccol + aRow < N)
            bv = *(const float4*)(W + (size_t)(ccol + aRow) * K + k0 + aCol);
        Bs[aCol + 0][aRow] = bv.x;
        Bs[aCol + 1][aRow] = bv.y;
        Bs[aCol + 2][aRow] = bv.z;
        Bs[aCol + 3][aRow] = bv.w;
        __syncthreads();

#pragma unroll
        for (int k = 0; k < 8; k++) {
            float4 a0 = *(const float4*)&As[k][tr * 8];
            float4 a1 = *(const float4*)&As[k][tr * 8 + 4];
            float4 b0 = *(const float4*)&Bs[k][tc * 8];
            float4 b1 = *(const float4*)&Bs[k][tc * 8 + 4];
            float am[8] = {a0.x, a0.y, a0.z, a0.w, a1.x, a1.y, a1.z, a1.w};
            float bn[8] = {b0.x, b0.y, b0.z, b0.w, b1.x, b1.y, b1.z, b1.w};
#pragma unroll
            for (int i = 0; i < 8; i++)
#pragma unroll
                for (int j = 0; j < 8; j++) acc[i][j] += am[i] * bn[j];
        }
        __syncthreads();
    }

    const int nbase = ccol + tc * 8;
    if (nbase < N) {
        float bb[8];
#pragma unroll
        for (int j = 0; j < 8; j++) bb[j] = bias[nbase + j];
#pragma unroll
        for (int i = 0; i < 8; i++) {
            const int m = crow + tr * 8 + i;
            float v[8];
#pragma unroll
            for (int j = 0; j < 8; j++) v[j] = leaky(acc[i][j] + bb[j]);
            float* cp = C + (size_t)m * N + nbase;
            *(float4*)(cp)     = make_float4(v[0], v[1], v[2], v[3]);
            *(float4*)(cp + 4) = make_float4(v[4], v[5], v[6], v[7]);
        }
    }
}

// ---------------------------------------------------------------------------
// TreeLayerNorm + LeakyReLU, in place. One CTA per sample.
// var uses ddof=1; eps added to STD (matches reference).
// ---------------------------------------------------------------------------
__global__ __launch_bounds__(256) void ln_leaky_k(float* __restrict__ t, int NT)
{
    float* p = t + (size_t)blockIdx.x * NT;
    const int tid = threadIdx.x;

    float s = 0.f, s2 = 0.f;
    for (int i = tid * 4; i < NT; i += 1024) {
        float4 v = *(const float4*)(p + i);
        s  += v.x + v.y + v.z + v.w;
        s2 += v.x * v.x + v.y * v.y + v.z * v.z + v.w * v.w;
    }
    __shared__ float sh[512];
    sh[tid] = s;
    sh[256 + tid] = s2;
    __syncthreads();
    for (int off = 128; off > 0; off >>= 1) {
        if (tid < off) {
            sh[tid]       += sh[tid + off];
            sh[256 + tid] += sh[256 + tid + off];
        }
        __syncthreads();
    }
    const float S = sh[0], S2 = sh[256];
    const float n = (float)NT;
    const float mean = S / n;
    float var = (S2 - S * mean) / (n - 1.f);
    var = fmaxf(var, 0.f);
    const float inv = 1.f / (sqrtf(var) + EPS);

    for (int i = tid * 4; i < NT; i += 1024) {
        float4 v = *(const float4*)(p + i);
        v.x = leaky((v.x - mean) * inv);
        v.y = leaky((v.y - mean) * inv);
        v.z = leaky((v.z - mean) * inv);
        v.w = leaky((v.w - mean) * inv);
        *(float4*)(p + i) = v;
    }
}

// ---------------------------------------------------------------------------
extern "C" void kernel_launch(void* const* d_in, const int* in_sizes, int n_in,
                              void* d_out, int out_size)
{
    const float* trees   = (const float*)d_in[0];
    const int*   indexes = (const int*)  d_in[1];
    const float* W1 = (const float*)d_in[2];  const float* b1 = (const float*)d_in[3];
    const float* W2 = (const float*)d_in[4];  const float* b2 = (const float*)d_in[5];
    const float* W3 = (const float*)d_in[6];  const float* b3 = (const float*)d_in[7];
    const float* W4 = (const float*)d_in[8];  const float* b4 = (const float*)d_in[9];
    const float* cw1 = (const float*)d_in[10]; const float* cb1 = (const float*)d_in[11];
    const float* cw2 = (const float*)d_in[12]; const float* cb2 = (const float*)d_in[13];
    const float* cw3 = (const float*)d_in[14]; const float* cb3 = (const float*)d_in[15];
    float* out = (float*)d_out;

    float *h1, *h2, *h3, *xx, *t1, *t2;
    cudaGetSymbolAddress((void**)&h1, g_h1);
    cudaGetSymbolAddress((void**)&h2, g_h2);
    cudaGetSymbolAddress((void**)&h3, g_h3);
    cudaGetSymbolAddress((void**)&xx, g_x);
    cudaGetSymbolAddress((void**)&t1, g_t1);
    cudaGetSymbolAddress((void**)&t2, g_t2);

    const int CONV_SMEM = (3072 * 4 + 2048 + 384) * 4;   // 58,880 B
    const int GEMM_SMEM = 4096 * 4 * 4;                  // 65,536 B
    cudaFuncSetAttribute(conv_mma<64, 128>,  cudaFuncAttributeMaxDynamicSharedMemorySize, CONV_SMEM);
    cudaFuncSetAttribute(conv_mma<128, 256>, cudaFuncAttributeMaxDynamicSharedMemorySize, CONV_SMEM);
    cudaFuncSetAttribute(conv_mma<256, 512>, cudaFuncAttributeMaxDynamicSharedMemorySize, CONV_SMEM);
    cudaFuncSetAttribute(gemm_mma,           cudaFuncAttributeMaxDynamicSharedMemorySize, GEMM_SMEM);

    // MLP stack (leaky fused); layers 2-4 on tensor cores
    sgemm_leaky_k<<<dim3(1, 32),  256>>>(BATCH,   64,   16, trees, W1, b1, h1);
    gemm_mma<<<dim3(2, 32),  256, GEMM_SMEM>>>(BATCH,  256,   64, h1, W2, b2, h2);
    gemm_mma<<<dim3(8, 32),  256, GEMM_SMEM>>>(BATCH, 1024,  256, h2, W3, b3, h3);
    gemm_mma<<<dim3(32, 32), 256, GEMM_SMEM>>>(BATCH, 4096, 1024, h3, W4, b4, xx);

    // Tree conv blocks on tensor cores: conv -> LayerNorm+Leaky
    conv_mma<64, 128> <<<dim3(1, BATCH / 2), 256, CONV_SMEM>>>(xx, indexes, cw1, cb1, t1);
    ln_leaky_k<<<BATCH, 256>>>(t1, 128 * 64);

    conv_mma<128, 256><<<dim3(2, BATCH / 2), 256, CONV_SMEM>>>(t1, indexes, cw2, cb2, t2);
    ln_leaky_k<<<BATCH, 256>>>(t2, 256 * 64);

    conv_mma<256, 512><<<dim3(4, BATCH / 2), 256, CONV_SMEM>>>(t2, indexes, cw3, cb3, out);
    ln_leaky_k<<<BATCH, 256>>>(out, 512 * 64);
}